// round 11
// baseline (speedup 1.0000x reference)
#include <cuda_runtime.h>

// Soft_NN forward == exact 1-NN: out[b,n,:] = y_c[b, argmin_m dist(x[b,n], y[b,m]), :]
// dist = fmaf(-2, s, fl(x2+y2)); s, x2, y2 sequential-k fp32 FMA chains —
// bit-identical to the R5 passing kernel (rel_err 0.0). Rounding unchanged.
// R10 == R9 resubmit (R9 bench was an infra failure, never measured):
//     8n x 4m per-thread tile (32 acc regs) so 512 threads fit the 128-reg cap:
//     4 warps/SMSP to hide LDS latency, pre-kernel norms, double-buffered Ys,
//     one barrier per chunk.

#define B_   4
#define N_   4096
#define M_   4096
#define C_   32
#define BN   128
#define BM   128
#define NTHR 512
#define NCHUNK (M_ / BM)      // 32
#define SSTR 132              // smem row stride (floats), 16B-aligned rows

typedef unsigned long long u64v;

__device__ float g_x2[B_ * N_];
__device__ float g_y2[B_ * M_];

static __device__ __forceinline__ u64v pack2(float lo, float hi) {
    u64v r;
    asm("mov.b64 %0, {%1, %2};" : "=l"(r)
        : "r"(__float_as_uint(lo)), "r"(__float_as_uint(hi)));
    return r;
}
static __device__ __forceinline__ u64v fma2(u64v a, u64v b, u64v c) {
    u64v d;
    asm("fma.rn.f32x2 %0, %1, %2, %3;" : "=l"(d) : "l"(a), "l"(b), "l"(c));
    return d;
}
static __device__ __forceinline__ u64v add2(u64v a, u64v b) {
    u64v d;
    asm("add.rn.f32x2 %0, %1, %2;" : "=l"(d) : "l"(a), "l"(b));
    return d;
}
static __device__ __forceinline__ void unpack2(u64v v, float& lo, float& hi) {
    unsigned ulo, uhi;
    asm("mov.b64 {%0, %1}, %2;" : "=r"(ulo), "=r"(uhi) : "l"(v));
    lo = __uint_as_float(ulo);
    hi = __uint_as_float(uhi);
}

// ---- pre-kernel: squared norms, sequential c-order chain (reference rounding) ----
__global__ void sq_norms_kernel(const float* __restrict__ x,
                                const float* __restrict__ y)
{
    int idx = blockIdx.x * blockDim.x + threadIdx.x;   // 0 .. 32767
    const float4* s4;
    float* dst;
    if (idx < B_ * N_) {
        s4 = (const float4*)(x + (size_t)idx * C_);
        dst = g_x2 + idx;
    } else {
        int r = idx - B_ * N_;
        s4 = (const float4*)(y + (size_t)r * C_);
        dst = g_y2 + r;
    }
    float s = 0.f;
    #pragma unroll
    for (int r = 0; r < 8; r++) {
        float4 v = s4[r];
        s = fmaf(v.x, v.x, s); s = fmaf(v.y, v.y, s);
        s = fmaf(v.z, v.z, s); s = fmaf(v.w, v.w, s);
    }
    *dst = s;
}

// smem (floats): Xs[32][SSTR] | Ys0[32][SSTR] | Ys1[32][SSTR]
#define SMEM_FLOATS (3 * C_ * SSTR)

__global__ __launch_bounds__(NTHR, 1)
void soft_nn_kernel(const float* __restrict__ x,
                    const float* __restrict__ y,
                    const float* __restrict__ yc,
                    float* __restrict__ out)
{
    extern __shared__ __align__(16) float smem[];
    float (*Xs)[SSTR] = (float(*)[SSTR])smem;            // transposed X tile
    float* YsBase = smem + C_ * SSTR;                    // two [C_][SSTR] buffers

    const int tid = threadIdx.x;
    const int tx  = tid & 31;        // 32 m-lanes, 4 m each
    const int ty  = tid >> 5;        // 16 n-lanes, 8 n each; constant per warp
    const int blk = blockIdx.x;      // 0..127
    const int b   = blk >> 5;
    const int n0  = (blk & 31) * BN;

    const float4* xg  = (const float4*)(x + ((size_t)b * N_ + n0) * C_);
    const float4* yg  = (const float4*)(y + (size_t)b * M_ * C_);
    const float*  y2g = g_y2 + b * M_;

    // ---- prologue: chunk0 LDG first (latency), then X tile transpose ----
    float4 pf[2];
    #pragma unroll
    for (int r = 0; r < 2; r++) pf[r] = yg[tid + NTHR * r];

    #pragma unroll
    for (int t = tid; t < BN * C_ / 4; t += NTHR) {
        int n  = t >> 3;             // 8 float4 per row (C=32)
        int c4 = (t & 7) << 2;
        float4 v = xg[t];
        Xs[c4 + 0][n] = v.x;
        Xs[c4 + 1][n] = v.y;
        Xs[c4 + 2][n] = v.z;
        Xs[c4 + 3][n] = v.w;
    }

    // x2 native pairs for this thread's 8 queries (pre-kernel output, 32B aligned)
    u64v x2p[4];
    {
        const ulonglong2* p = (const ulonglong2*)(g_x2 + b * N_ + n0 + ty * 8);
        ulonglong2 a = p[0], c = p[1];
        x2p[0] = a.x; x2p[1] = a.y; x2p[2] = c.x; x2p[3] = c.y;
    }

    // store chunk0 into buffer 0
    #pragma unroll
    for (int r = 0; r < 2; r++) {
        int t  = tid + NTHR * r;
        int m  = t >> 3;
        int c4 = (t & 7) << 2;
        float4 v = pf[r];
        YsBase[(c4 + 0) * SSTR + m] = v.x;
        YsBase[(c4 + 1) * SSTR + m] = v.y;
        YsBase[(c4 + 2) * SSTR + m] = v.z;
        YsBase[(c4 + 3) * SSTR + m] = v.w;
    }
    __syncthreads();

    const u64v NEG2 = pack2(-2.0f, -2.0f);

    float bestd[8];
    int   bestm[8];
    #pragma unroll
    for (int i = 0; i < 8; i++) { bestd[i] = 3.4e38f; bestm[i] = 0; }

    for (int ic = 0; ic < NCHUNK; ic++) {
        const int mc = ic * BM;
        const float* Yc = YsBase + (ic & 1) * (C_ * SSTR);

        // prefetch next chunk (consumed after compute; latency hidden)
        if (ic + 1 < NCHUNK) {
            const float4* ygn = yg + ((mc + BM) * C_) / 4;
            #pragma unroll
            for (int r = 0; r < 2; r++) pf[r] = ygn[tid + NTHR * r];
        }

        // y2 for this thread's 4 candidates (L2-resident, one LDG.128)
        float4 yy = *(const float4*)(y2g + mc + tx * 4);
        float yyr[4] = { yy.x, yy.y, yy.z, yy.w };

        // ---- mainloop: per k = 2 LDS.128(x,bcast) + 1 LDS.128(y) + 4 packs + 16 FFMA2 ----
        u64v acc[4][4];
        #pragma unroll
        for (int i2 = 0; i2 < 4; i2++)
            #pragma unroll
            for (int j = 0; j < 4; j++) acc[i2][j] = 0ULL;

        #pragma unroll 8
        for (int k = 0; k < C_; k++) {
            ulonglong2 xp = *(const ulonglong2*)&Xs[k][ty * 8];       // (x0,x1),(x2,x3)
            ulonglong2 xq = *(const ulonglong2*)&Xs[k][ty * 8 + 4];   // (x4,x5),(x6,x7)
            float4 ya = *(const float4*)&Yc[k * SSTR + tx * 4];       // 4 m values
            u64v xv[4] = { xp.x, xp.y, xq.x, xq.y };
            u64v yp[4] = { pack2(ya.x, ya.x), pack2(ya.y, ya.y),
                           pack2(ya.z, ya.z), pack2(ya.w, ya.w) };
            #pragma unroll
            for (int i2 = 0; i2 < 4; i2++)
                #pragma unroll
                for (int j = 0; j < 4; j++)
                    acc[i2][j] = fma2(xv[i2], yp[j], acc[i2][j]);
        }

        // ---- packed epilogue: d2 = fma2(acc, -2, add2(x2pair, y2dup)) ----
        // lane-wise identical to fmaf(-2, s, __fadd_rn(x2, y2)).
        #pragma unroll
        for (int j = 0; j < 4; j++) {
            int   m   = mc + tx * 4 + j;
            u64v  y2d = pack2(yyr[j], yyr[j]);
            #pragma unroll
            for (int i2 = 0; i2 < 4; i2++) {
                u64v d2 = fma2(acc[i2][j], NEG2, add2(x2p[i2], y2d));
                float dlo, dhi;
                unpack2(d2, dlo, dhi);
                // per n-slot, m ascends across j and chunks: strict < keeps earliest m
                if (dlo < bestd[2 * i2])     { bestd[2 * i2]     = dlo; bestm[2 * i2]     = m; }
                if (dhi < bestd[2 * i2 + 1]) { bestd[2 * i2 + 1] = dhi; bestm[2 * i2 + 1] = m; }
            }
        }

        // ---- store next chunk into the other buffer (read last in ic-1) ----
        if (ic + 1 < NCHUNK) {
            float* Yn = YsBase + ((ic + 1) & 1) * (C_ * SSTR);
            #pragma unroll
            for (int r = 0; r < 2; r++) {
                int t  = tid + NTHR * r;
                int m  = t >> 3;
                int c4 = (t & 7) << 2;
                float4 v = pf[r];
                Yn[(c4 + 0) * SSTR + m] = v.x;
                Yn[(c4 + 1) * SSTR + m] = v.y;
                Yn[(c4 + 2) * SSTR + m] = v.z;
                Yn[(c4 + 3) * SSTR + m] = v.w;
            }
        }
        __syncthreads();   // single barrier per chunk
    }

    // ---- cross-tx reduction (reuse smem as scratch) ----
    float* redD = smem;                    // BN*32 = 4096 floats
    int*   redM = (int*)(smem + BN * 32);  // 4096 ints
    #pragma unroll
    for (int i = 0; i < 8; i++) {
        int n = ty * 8 + i;
        redD[n * 32 + tx] = bestd[i];
        redM[n * 32 + tx] = bestm[i];
    }
    __syncthreads();
    if (tid < BN) {
        float bd = redD[tid * 32];
        int   bm = redM[tid * 32];
        #pragma unroll
        for (int t = 1; t < 32; t++) {
            float d = redD[tid * 32 + t];
            int   m = redM[tid * 32 + t];
            if (d < bd || (d == bd && m < bm)) { bd = d; bm = m; }
        }
        const float* src = yc + ((size_t)b * M_ + bm) * 3;
        float*       dst = out + ((size_t)b * N_ + n0 + tid) * 3;
        dst[0] = src[0];
        dst[1] = src[1];
        dst[2] = src[2];
    }
}

extern "C" void kernel_launch(void* const* d_in, const int* in_sizes, int n_in,
                              void* d_out, int out_size)
{
    const float* x  = (const float*)d_in[0];   // x_f  [4,4096,32]
    const float* y  = (const float*)d_in[1];   // y_f  [4,4096,32]
    const float* yc = (const float*)d_in[2];   // y_c  [4,4096,3]
    // d_in[3] = temp_inv (positive constant; does not affect argmax)
    float* out = (float*)d_out;                // [4,4096,3]

    sq_norms_kernel<<<(B_ * (N_ + M_)) / 256, 256>>>(x, y);

    const int smem_bytes = SMEM_FLOATS * (int)sizeof(float);  // ~50.7KB
    cudaFuncSetAttribute(soft_nn_kernel,
                         cudaFuncAttributeMaxDynamicSharedMemorySize, smem_bytes);
    soft_nn_kernel<<<(B_ * N_) / BN, NTHR, smem_bytes>>>(x, y, yc, out);
}

// round 12
// speedup vs baseline: 1.8305x; 1.8305x over previous
#include <cuda_runtime.h>

// Soft_NN forward == exact 1-NN: out[b,n,:] = y_c[b, argmin_m dist(x[b,n], y[b,m]), :]
// dist lane-wise = fmaf(-2, s, fl(x2+y2)); s, x2, y2 sequential fp32 FMA chains —
// bit-identical to the R5 passing kernel (rel_err 0.0).
// R11 = R5 config (256 thr, 8x8 tile, FFMA2 pairs-along-n — the proven-fast shape)
//       + pre-kernel norms + double-buffered Ys (1 barrier/chunk) + packed epilogue.
//       512-thread variants abandoned: reg-pair pressure makes ptxas split
//       fma.rn.f32x2 into 2xFFMA (R10: fma-cycles 98us-equiv vs R5's 58).

#define B_   4
#define N_   4096
#define M_   4096
#define C_   32
#define BN   128
#define BM   128
#define NTHR 256
#define NCHUNK (M_ / BM)      // 32
#define SSTR 132              // smem row stride (floats), 16B-aligned rows

typedef unsigned long long u64v;

__device__ float g_x2[B_ * N_];
__device__ float g_y2[B_ * M_];

static __device__ __forceinline__ u64v pack2(float lo, float hi) {
    u64v r;
    asm("mov.b64 %0, {%1, %2};" : "=l"(r)
        : "r"(__float_as_uint(lo)), "r"(__float_as_uint(hi)));
    return r;
}
static __device__ __forceinline__ u64v fma2(u64v a, u64v b, u64v c) {
    u64v d;
    asm("fma.rn.f32x2 %0, %1, %2, %3;" : "=l"(d) : "l"(a), "l"(b), "l"(c));
    return d;
}
static __device__ __forceinline__ u64v add2(u64v a, u64v b) {
    u64v d;
    asm("add.rn.f32x2 %0, %1, %2;" : "=l"(d) : "l"(a), "l"(b));
    return d;
}
static __device__ __forceinline__ void unpack2(u64v v, float& lo, float& hi) {
    unsigned ulo, uhi;
    asm("mov.b64 {%0, %1}, %2;" : "=r"(ulo), "=r"(uhi) : "l"(v));
    lo = __uint_as_float(ulo);
    hi = __uint_as_float(uhi);
}

// ---- pre-kernel: squared norms, sequential c-order chain (reference rounding) ----
__global__ void sq_norms_kernel(const float* __restrict__ x,
                                const float* __restrict__ y)
{
    int idx = blockIdx.x * blockDim.x + threadIdx.x;   // 0 .. 32767
    const float4* s4;
    float* dst;
    if (idx < B_ * N_) {
        s4 = (const float4*)(x + (size_t)idx * C_);
        dst = g_x2 + idx;
    } else {
        int r = idx - B_ * N_;
        s4 = (const float4*)(y + (size_t)r * C_);
        dst = g_y2 + r;
    }
    float s = 0.f;
    #pragma unroll
    for (int r = 0; r < 8; r++) {
        float4 v = s4[r];
        s = fmaf(v.x, v.x, s); s = fmaf(v.y, v.y, s);
        s = fmaf(v.z, v.z, s); s = fmaf(v.w, v.w, s);
    }
    *dst = s;
}

// smem (floats): Xs[32][SSTR] | Ys0[32][SSTR] | Ys1[32][SSTR]
#define SMEM_FLOATS (3 * C_ * SSTR)

__global__ __launch_bounds__(NTHR, 1)
void soft_nn_kernel(const float* __restrict__ x,
                    const float* __restrict__ y,
                    const float* __restrict__ yc,
                    float* __restrict__ out)
{
    extern __shared__ __align__(16) float smem[];
    float (*Xs)[SSTR] = (float(*)[SSTR])smem;            // transposed X tile
    float* YsBase = smem + C_ * SSTR;                    // two [C_][SSTR] buffers

    const int tid = threadIdx.x;
    const int tx  = tid & 15;        // 16 m-lanes, 8 m each
    const int ty  = tid >> 4;        // 16 n-lanes, 8 n each
    const int blk = blockIdx.x;      // 0..127
    const int b   = blk >> 5;
    const int n0  = (blk & 31) * BN;

    const float4* xg  = (const float4*)(x + ((size_t)b * N_ + n0) * C_);
    const float4* yg  = (const float4*)(y + (size_t)b * M_ * C_);
    const float*  y2g = g_y2 + b * M_;

    // ---- prologue: chunk0 LDG first (latency), then X tile transpose ----
    float4 pf[4];
    #pragma unroll
    for (int r = 0; r < 4; r++) pf[r] = yg[tid + NTHR * r];

    #pragma unroll
    for (int t = tid; t < BN * C_ / 4; t += NTHR) {
        int n  = t >> 3;             // 8 float4 per row (C=32)
        int c4 = (t & 7) << 2;
        float4 v = xg[t];
        Xs[c4 + 0][n] = v.x;
        Xs[c4 + 1][n] = v.y;
        Xs[c4 + 2][n] = v.z;
        Xs[c4 + 3][n] = v.w;
    }

    // x2 native pairs for this thread's 8 queries (pre-kernel output, 32B aligned)
    u64v x2p[4];
    {
        const ulonglong2* p = (const ulonglong2*)(g_x2 + b * N_ + n0 + ty * 8);
        ulonglong2 a = p[0], c = p[1];
        x2p[0] = a.x; x2p[1] = a.y; x2p[2] = c.x; x2p[3] = c.y;
    }

    // store chunk0 into buffer 0
    #pragma unroll
    for (int r = 0; r < 4; r++) {
        int t  = tid + NTHR * r;
        int m  = t >> 3;
        int c4 = (t & 7) << 2;
        float4 v = pf[r];
        YsBase[(c4 + 0) * SSTR + m] = v.x;
        YsBase[(c4 + 1) * SSTR + m] = v.y;
        YsBase[(c4 + 2) * SSTR + m] = v.z;
        YsBase[(c4 + 3) * SSTR + m] = v.w;
    }
    __syncthreads();

    const u64v NEG2 = pack2(-2.0f, -2.0f);

    float bestd[8];
    int   bestm[8];
    #pragma unroll
    for (int i = 0; i < 8; i++) { bestd[i] = 3.4e38f; bestm[i] = 0; }

    for (int ic = 0; ic < NCHUNK; ic++) {
        const int mc = ic * BM;
        const float* Yc = YsBase + (ic & 1) * (C_ * SSTR);

        // prefetch next chunk (consumed after compute; latency hidden)
        if (ic + 1 < NCHUNK) {
            const float4* ygn = yg + ((mc + BM) * C_) / 4;
            #pragma unroll
            for (int r = 0; r < 4; r++) pf[r] = ygn[tid + NTHR * r];
        }

        // y2 for this thread's 8 candidates (L2-resident, two LDG.128)
        float4 yya = *(const float4*)(y2g + mc + tx * 4);
        float4 yyb = *(const float4*)(y2g + mc + 64 + tx * 4);
        float yyr[8] = { yya.x, yya.y, yya.z, yya.w,
                         yyb.x, yyb.y, yyb.z, yyb.w };

        // ---- R5 mainloop (verbatim): packed 8x8 tile, FFMA2 pairs along n ----
        // thread's candidates: m = mc + tx*4 + j (j<4), mc + 64 + tx*4 + (j-4)
        u64v acc[4][8];
        #pragma unroll
        for (int i2 = 0; i2 < 4; i2++)
            #pragma unroll
            for (int j = 0; j < 8; j++) acc[i2][j] = 0ULL;

        #pragma unroll 8
        for (int k = 0; k < C_; k++) {
            ulonglong2 xp = *(const ulonglong2*)&Xs[k][ty * 8];       // (x0,x1),(x2,x3)
            ulonglong2 xq = *(const ulonglong2*)&Xs[k][ty * 8 + 4];   // (x4,x5),(x6,x7)
            float4 ya = *(const float4*)&Yc[k * SSTR + tx * 4];       // conflict-free
            float4 yb = *(const float4*)&Yc[k * SSTR + 64 + tx * 4];  // conflict-free
            u64v xpair[4] = { xp.x, xp.y, xq.x, xq.y };
            u64v yp[8] = {
                pack2(ya.x, ya.x), pack2(ya.y, ya.y), pack2(ya.z, ya.z), pack2(ya.w, ya.w),
                pack2(yb.x, yb.x), pack2(yb.y, yb.y), pack2(yb.z, yb.z), pack2(yb.w, yb.w)
            };
            #pragma unroll
            for (int i2 = 0; i2 < 4; i2++)
                #pragma unroll
                for (int j = 0; j < 8; j++)
                    acc[i2][j] = fma2(xpair[i2], yp[j], acc[i2][j]);
        }

        // ---- packed epilogue: d2 = fma2(acc, -2, add2(x2pair, y2dup)) ----
        // lane-wise identical to fmaf(-2, s, __fadd_rn(x2, y2)).
        #pragma unroll
        for (int j = 0; j < 8; j++) {
            int  m   = mc + ((j < 4) ? (tx * 4 + j) : (64 + tx * 4 + (j - 4)));
            u64v y2d = pack2(yyr[j], yyr[j]);
            #pragma unroll
            for (int i2 = 0; i2 < 4; i2++) {
                u64v d2 = fma2(acc[i2][j], NEG2, add2(x2p[i2], y2d));
                float dlo, dhi;
                unpack2(d2, dlo, dhi);
                // per n-slot, m ascends across j and chunks: strict < keeps earliest m
                if (dlo < bestd[2 * i2])     { bestd[2 * i2]     = dlo; bestm[2 * i2]     = m; }
                if (dhi < bestd[2 * i2 + 1]) { bestd[2 * i2 + 1] = dhi; bestm[2 * i2 + 1] = m; }
            }
        }

        // ---- store next chunk into the other buffer (that buffer was read
        //      last during chunk ic-1; barrier below orders the reuse) ----
        if (ic + 1 < NCHUNK) {
            float* Yn = YsBase + ((ic + 1) & 1) * (C_ * SSTR);
            #pragma unroll
            for (int r = 0; r < 4; r++) {
                int t  = tid + NTHR * r;
                int m  = t >> 3;
                int c4 = (t & 7) << 2;
                float4 v = pf[r];
                Yn[(c4 + 0) * SSTR + m] = v.x;
                Yn[(c4 + 1) * SSTR + m] = v.y;
                Yn[(c4 + 2) * SSTR + m] = v.z;
                Yn[(c4 + 3) * SSTR + m] = v.w;
            }
        }
        __syncthreads();   // single barrier per chunk
    }

    // ---- cross-tx reduction (reuse smem as scratch) ----
    float* redD = smem;                    // BN*16 = 2048 floats
    int*   redM = (int*)(smem + BN * 16);  // 2048 ints
    #pragma unroll
    for (int i = 0; i < 8; i++) {
        int n = ty * 8 + i;
        redD[n * 16 + tx] = bestd[i];
        redM[n * 16 + tx] = bestm[i];
    }
    __syncthreads();
    if (tid < BN) {
        float bd = redD[tid * 16];
        int   bm = redM[tid * 16];
        #pragma unroll
        for (int t = 1; t < 16; t++) {
            float d = redD[tid * 16 + t];
            int   m = redM[tid * 16 + t];
            if (d < bd || (d == bd && m < bm)) { bd = d; bm = m; }
        }
        const float* src = yc + ((size_t)b * M_ + bm) * 3;
        float*       dst = out + ((size_t)b * N_ + n0 + tid) * 3;
        dst[0] = src[0];
        dst[1] = src[1];
        dst[2] = src[2];
    }
}

extern "C" void kernel_launch(void* const* d_in, const int* in_sizes, int n_in,
                              void* d_out, int out_size)
{
    const float* x  = (const float*)d_in[0];   // x_f  [4,4096,32]
    const float* y  = (const float*)d_in[1];   // y_f  [4,4096,32]
    const float* yc = (const float*)d_in[2];   // y_c  [4,4096,3]
    // d_in[3] = temp_inv (positive constant; does not affect argmax)
    float* out = (float*)d_out;                // [4,4096,3]

    sq_norms_kernel<<<(B_ * (N_ + M_)) / 256, 256>>>(x, y);

    const int smem_bytes = SMEM_FLOATS * (int)sizeof(float);  // ~50.7KB
    cudaFuncSetAttribute(soft_nn_kernel,
                         cudaFuncAttributeMaxDynamicSharedMemorySize, smem_bytes);
    soft_nn_kernel<<<(B_ * N_) / BN, NTHR, smem_bytes>>>(x, y, yc, out);
}

// round 14
// speedup vs baseline: 1.8630x; 1.0178x over previous
#include <cuda_runtime.h>

// Soft_NN forward == exact 1-NN: out[b,n,:] = y_c[b, argmin_m dist(x[b,n], y[b,m]), :]
// dist lane-wise = fmaf(-2, s, fl(x2+y2)); s, x2, y2 sequential fp32 FMA chains —
// bit-identical to the R5/R11 passing kernels (rel_err 0.0).
// R12 = R11 + manually software-pipelined mainloop: LDS for k+1 issued before the
//       FFMA2 block for k (register double-buffer, full unroll) so the
//       LDS(29cyc)->pack->FFMA2 chain is covered by the previous iteration's math.

#define B_   4
#define N_   4096
#define M_   4096
#define C_   32
#define BN   128
#define BM   128
#define NTHR 256
#define NCHUNK (M_ / BM)      // 32
#define SSTR 132              // smem row stride (floats), 16B-aligned rows

typedef unsigned long long u64v;

__device__ float g_x2[B_ * N_];
__device__ float g_y2[B_ * M_];

static __device__ __forceinline__ u64v pack2(float lo, float hi) {
    u64v r;
    asm("mov.b64 %0, {%1, %2};" : "=l"(r)
        : "r"(__float_as_uint(lo)), "r"(__float_as_uint(hi)));
    return r;
}
static __device__ __forceinline__ u64v fma2(u64v a, u64v b, u64v c) {
    u64v d;
    asm("fma.rn.f32x2 %0, %1, %2, %3;" : "=l"(d) : "l"(a), "l"(b), "l"(c));
    return d;
}
static __device__ __forceinline__ u64v add2(u64v a, u64v b) {
    u64v d;
    asm("add.rn.f32x2 %0, %1, %2;" : "=l"(d) : "l"(a), "l"(b));
    return d;
}
static __device__ __forceinline__ void unpack2(u64v v, float& lo, float& hi) {
    unsigned ulo, uhi;
    asm("mov.b64 {%0, %1}, %2;" : "=r"(ulo), "=r"(uhi) : "l"(v));
    lo = __uint_as_float(ulo);
    hi = __uint_as_float(uhi);
}

// ---- pre-kernel: squared norms, sequential c-order chain (reference rounding) ----
__global__ void sq_norms_kernel(const float* __restrict__ x,
                                const float* __restrict__ y)
{
    int idx = blockIdx.x * blockDim.x + threadIdx.x;   // 0 .. 32767
    const float4* s4;
    float* dst;
    if (idx < B_ * N_) {
        s4 = (const float4*)(x + (size_t)idx * C_);
        dst = g_x2 + idx;
    } else {
        int r = idx - B_ * N_;
        s4 = (const float4*)(y + (size_t)r * C_);
        dst = g_y2 + r;
    }
    float s = 0.f;
    #pragma unroll
    for (int r = 0; r < 8; r++) {
        float4 v = s4[r];
        s = fmaf(v.x, v.x, s); s = fmaf(v.y, v.y, s);
        s = fmaf(v.z, v.z, s); s = fmaf(v.w, v.w, s);
    }
    *dst = s;
}

// smem (floats): Xs[32][SSTR] | Ys0[32][SSTR] | Ys1[32][SSTR]
#define SMEM_FLOATS (3 * C_ * SSTR)

__global__ __launch_bounds__(NTHR, 1)
void soft_nn_kernel(const float* __restrict__ x,
                    const float* __restrict__ y,
                    const float* __restrict__ yc,
                    float* __restrict__ out)
{
    extern __shared__ __align__(16) float smem[];
    float (*Xs)[SSTR] = (float(*)[SSTR])smem;            // transposed X tile
    float* YsBase = smem + C_ * SSTR;                    // two [C_][SSTR] buffers

    const int tid = threadIdx.x;
    const int tx  = tid & 15;        // 16 m-lanes, 8 m each
    const int ty  = tid >> 4;        // 16 n-lanes, 8 n each
    const int blk = blockIdx.x;      // 0..127
    const int b   = blk >> 5;
    const int n0  = (blk & 31) * BN;

    const float4* xg  = (const float4*)(x + ((size_t)b * N_ + n0) * C_);
    const float4* yg  = (const float4*)(y + (size_t)b * M_ * C_);
    const float*  y2g = g_y2 + b * M_;

    // ---- prologue: chunk0 LDG first (latency), then X tile transpose ----
    float4 pf[4];
    #pragma unroll
    for (int r = 0; r < 4; r++) pf[r] = yg[tid + NTHR * r];

    #pragma unroll
    for (int t = tid; t < BN * C_ / 4; t += NTHR) {
        int n  = t >> 3;             // 8 float4 per row (C=32)
        int c4 = (t & 7) << 2;
        float4 v = xg[t];
        Xs[c4 + 0][n] = v.x;
        Xs[c4 + 1][n] = v.y;
        Xs[c4 + 2][n] = v.z;
        Xs[c4 + 3][n] = v.w;
    }

    // x2 native pairs for this thread's 8 queries (pre-kernel output, 32B aligned)
    u64v x2p[4];
    {
        const ulonglong2* p = (const ulonglong2*)(g_x2 + b * N_ + n0 + ty * 8);
        ulonglong2 a = p[0], c = p[1];
        x2p[0] = a.x; x2p[1] = a.y; x2p[2] = c.x; x2p[3] = c.y;
    }

    // store chunk0 into buffer 0
    #pragma unroll
    for (int r = 0; r < 4; r++) {
        int t  = tid + NTHR * r;
        int m  = t >> 3;
        int c4 = (t & 7) << 2;
        float4 v = pf[r];
        YsBase[(c4 + 0) * SSTR + m] = v.x;
        YsBase[(c4 + 1) * SSTR + m] = v.y;
        YsBase[(c4 + 2) * SSTR + m] = v.z;
        YsBase[(c4 + 3) * SSTR + m] = v.w;
    }
    __syncthreads();

    const u64v NEG2 = pack2(-2.0f, -2.0f);

    float bestd[8];
    int   bestm[8];
    #pragma unroll
    for (int i = 0; i < 8; i++) { bestd[i] = 3.4e38f; bestm[i] = 0; }

    for (int ic = 0; ic < NCHUNK; ic++) {
        const int mc = ic * BM;
        const float* Yc = YsBase + (ic & 1) * (C_ * SSTR);

        // prefetch next chunk (consumed after compute; latency hidden)
        if (ic + 1 < NCHUNK) {
            const float4* ygn = yg + ((mc + BM) * C_) / 4;
            #pragma unroll
            for (int r = 0; r < 4; r++) pf[r] = ygn[tid + NTHR * r];
        }

        // y2 for this thread's 8 candidates (L2-resident, two LDG.128)
        float4 yya = *(const float4*)(y2g + mc + tx * 4);
        float4 yyb = *(const float4*)(y2g + mc + 64 + tx * 4);
        float yyr[8] = { yya.x, yya.y, yya.z, yya.w,
                         yyb.x, yyb.y, yyb.z, yyb.w };

        // ---- software-pipelined mainloop: LDS for k+1 before FFMA2 for k ----
        // FFMA2 order per lane identical to R11 (bit-identical distances).
        u64v acc[4][8];
        #pragma unroll
        for (int i2 = 0; i2 < 4; i2++)
            #pragma unroll
            for (int j = 0; j < 8; j++) acc[i2][j] = 0ULL;

        // preload k = 0
        u64v  xc[4];
        float yac[8];
        {
            ulonglong2 xp = *(const ulonglong2*)&Xs[0][ty * 8];
            ulonglong2 xq = *(const ulonglong2*)&Xs[0][ty * 8 + 4];
            float4 ya = *(const float4*)&Yc[tx * 4];
            float4 yb = *(const float4*)&Yc[64 + tx * 4];
            xc[0] = xp.x; xc[1] = xp.y; xc[2] = xq.x; xc[3] = xq.y;
            yac[0] = ya.x; yac[1] = ya.y; yac[2] = ya.z; yac[3] = ya.w;
            yac[4] = yb.x; yac[5] = yb.y; yac[6] = yb.z; yac[7] = yb.w;
        }

        #pragma unroll
        for (int k = 0; k < C_; k++) {
            // issue k+1 loads first (consumed next iteration; 29cyc LDS latency
            // covered by the 32 FFMA2 below)
            u64v  xn[4];
            float yan[8];
            if (k + 1 < C_) {
                ulonglong2 xp = *(const ulonglong2*)&Xs[k + 1][ty * 8];
                ulonglong2 xq = *(const ulonglong2*)&Xs[k + 1][ty * 8 + 4];
                float4 ya = *(const float4*)&Yc[(k + 1) * SSTR + tx * 4];
                float4 yb = *(const float4*)&Yc[(k + 1) * SSTR + 64 + tx * 4];
                xn[0] = xp.x; xn[1] = xp.y; xn[2] = xq.x; xn[3] = xq.y;
                yan[0] = ya.x; yan[1] = ya.y; yan[2] = ya.z; yan[3] = ya.w;
                yan[4] = yb.x; yan[5] = yb.y; yan[6] = yb.z; yan[7] = yb.w;
            }

            u64v yp[8] = {
                pack2(yac[0], yac[0]), pack2(yac[1], yac[1]),
                pack2(yac[2], yac[2]), pack2(yac[3], yac[3]),
                pack2(yac[4], yac[4]), pack2(yac[5], yac[5]),
                pack2(yac[6], yac[6]), pack2(yac[7], yac[7])
            };
            #pragma unroll
            for (int i2 = 0; i2 < 4; i2++)
                #pragma unroll
                for (int j = 0; j < 8; j++)
                    acc[i2][j] = fma2(xc[i2], yp[j], acc[i2][j]);

            // rotate (register renames after full unroll)
            if (k + 1 < C_) {
                #pragma unroll
                for (int i2 = 0; i2 < 4; i2++) xc[i2] = xn[i2];
                #pragma unroll
                for (int j = 0; j < 8; j++) yac[j] = yan[j];
            }
        }

        // ---- packed epilogue: d2 = fma2(acc, -2, add2(x2pair, y2dup)) ----
        // lane-wise identical to fmaf(-2, s, __fadd_rn(x2, y2)).
        #pragma unroll
        for (int j = 0; j < 8; j++) {
            int  m   = mc + ((j < 4) ? (tx * 4 + j) : (64 + tx * 4 + (j - 4)));
            u64v y2d = pack2(yyr[j], yyr[j]);
            #pragma unroll
            for (int i2 = 0; i2 < 4; i2++) {
                u64v d2 = fma2(acc[i2][j], NEG2, add2(x2p[i2], y2d));
                float dlo, dhi;
                unpack2(d2, dlo, dhi);
                // per n-slot, m ascends across j and chunks: strict < keeps earliest m
                if (dlo < bestd[2 * i2])     { bestd[2 * i2]     = dlo; bestm[2 * i2]     = m; }
                if (dhi < bestd[2 * i2 + 1]) { bestd[2 * i2 + 1] = dhi; bestm[2 * i2 + 1] = m; }
            }
        }

        // ---- store next chunk into the other buffer (read last in ic-1;
        //      barrier below orders the reuse) ----
        if (ic + 1 < NCHUNK) {
            float* Yn = YsBase + ((ic + 1) & 1) * (C_ * SSTR);
            #pragma unroll
            for (int r = 0; r < 4; r++) {
                int t  = tid + NTHR * r;
                int m  = t >> 3;
                int c4 = (t & 7) << 2;
                float4 v = pf[r];
                Yn[(c4 + 0) * SSTR + m] = v.x;
                Yn[(c4 + 1) * SSTR + m] = v.y;
                Yn[(c4 + 2) * SSTR + m] = v.z;
                Yn[(c4 + 3) * SSTR + m] = v.w;
            }
        }
        __syncthreads();   // single barrier per chunk
    }

    // ---- cross-tx reduction (reuse smem as scratch) ----
    float* redD = smem;                    // BN*16 = 2048 floats
    int*   redM = (int*)(smem + BN * 16);  // 2048 ints
    #pragma unroll
    for (int i = 0; i < 8; i++) {
        int n = ty * 8 + i;
        redD[n * 16 + tx] = bestd[i];
        redM[n * 16 + tx] = bestm[i];
    }
    __syncthreads();
    if (tid < BN) {
        float bd = redD[tid * 16];
        int   bm = redM[tid * 16];
        #pragma unroll
        for (int t = 1; t < 16; t++) {
            float d = redD[tid * 16 + t];
            int   m = redM[tid * 16 + t];
            if (d < bd || (d == bd && m < bm)) { bd = d; bm = m; }
        }
        const float* src = yc + ((size_t)b * M_ + bm) * 3;
        float*       dst = out + ((size_t)b * N_ + n0 + tid) * 3;
        dst[0] = src[0];
        dst[1] = src[1];
        dst[2] = src[2];
    }
}

extern "C" void kernel_launch(void* const* d_in, const int* in_sizes, int n_in,
                              void* d_out, int out_size)
{
    const float* x  = (const float*)d_in[0];   // x_f  [4,4096,32]
    const float* y  = (const float*)d_in[1];   // y_f  [4,4096,32]
    const float* yc = (const float*)d_in[2];   // y_c  [4,4096,3]
    // d_in[3] = temp_inv (positive constant; does not affect argmax)
    float* out = (float*)d_out;                // [4,4096,3]

    sq_norms_kernel<<<(B_ * (N_ + M_)) / 256, 256>>>(x, y);

    const int smem_bytes = SMEM_FLOATS * (int)sizeof(float);  // ~50.7KB
    cudaFuncSetAttribute(soft_nn_kernel,
                         cudaFuncAttributeMaxDynamicSharedMemorySize, smem_bytes);
    soft_nn_kernel<<<(B_ * N_) / BN, NTHR, smem_bytes>>>(x, y, yc, out);
}